// round 10
// baseline (speedup 1.0000x reference)
#include <cuda_runtime.h>
#include <cuda_bf16.h>
#include <cstdint>

// Problem constants
#define BATCH   2
#define SEQ     2048
#define DIMV    4096
#define HQ      32
#define HKV     8
#define HD      128
#define ROWS    (BATCH * SEQ)      // 4096
#define KVDIM   (HKV * HD)         // 1024

// ---------------------------------------------------------------------------
// Device scratch (allocation-free rule)
// ---------------------------------------------------------------------------
__device__ __nv_bfloat16 g_xhi[ROWS * DIMV],  g_xlo[ROWS * DIMV];
__device__ __nv_bfloat16 g_qhi[ROWS * DIMV],  g_qlo[ROWS * DIMV];
__device__ __nv_bfloat16 g_khi[ROWS * KVDIM], g_klo[ROWS * KVDIM];
__device__ __nv_bfloat16 g_vhi[ROWS * KVDIM], g_vlo[ROWS * KVDIM];
__device__ __nv_bfloat16 g_ahi[ROWS * DIMV],  g_alo[ROWS * DIMV];
__device__ __nv_bfloat16 g_wqThi[DIMV * DIMV],  g_wqTlo[DIMV * DIMV];
__device__ __nv_bfloat16 g_wkThi[KVDIM * DIMV], g_wkTlo[KVDIM * DIMV];
__device__ __nv_bfloat16 g_wvThi[KVDIM * DIMV], g_wvTlo[KVDIM * DIMV];
__device__ __nv_bfloat16 g_woThi[DIMV * DIMV],  g_woTlo[DIMV * DIMV];

// ---------------------------------------------------------------------------
// Arch-generic PTX helpers (NO 'a'-gated instructions: sm_103 virtual target)
// ---------------------------------------------------------------------------
__device__ __forceinline__ uint32_t smem_u32(const void* p) {
    uint32_t a;
    asm("{ .reg .u64 t; cvta.to.shared.u64 t, %1; cvt.u32.u64 %0, t; }"
        : "=r"(a) : "l"(p));
    return a;
}

#define CP_ASYNC16(saddr, gptr) \
    asm volatile("cp.async.cg.shared.global [%0], [%1], 16;" \
        :: "r"(saddr), "l"(gptr) : "memory")
#define CP_COMMIT()  asm volatile("cp.async.commit_group;" ::: "memory")
#define CP_WAIT2()   asm volatile("cp.async.wait_group 2;" ::: "memory")
#define CP_WAIT1()   asm volatile("cp.async.wait_group 1;" ::: "memory")
#define CP_WAIT0()   asm volatile("cp.async.wait_group 0;" ::: "memory")

__device__ __forceinline__ void ldsm4(uint32_t* r, uint32_t addr) {
    asm volatile("ldmatrix.sync.aligned.m8n8.x4.shared.b16 {%0,%1,%2,%3}, [%4];"
        : "=r"(r[0]), "=r"(r[1]), "=r"(r[2]), "=r"(r[3]) : "r"(addr));
}
__device__ __forceinline__ void ldsm4t(uint32_t* r, uint32_t addr) {
    asm volatile("ldmatrix.sync.aligned.m8n8.x4.trans.shared.b16 {%0,%1,%2,%3}, [%4];"
        : "=r"(r[0]), "=r"(r[1]), "=r"(r[2]), "=r"(r[3]) : "r"(addr));
}

__device__ __forceinline__ void mma16816(float* d, const uint32_t* a, const uint32_t* b) {
    asm volatile("mma.sync.aligned.m16n8k16.row.col.f32.bf16.bf16.f32 "
        "{%0,%1,%2,%3}, {%4,%5,%6,%7}, {%8,%9}, {%0,%1,%2,%3};"
        : "+f"(d[0]), "+f"(d[1]), "+f"(d[2]), "+f"(d[3])
        : "r"(a[0]), "r"(a[1]), "r"(a[2]), "r"(a[3]), "r"(b[0]), "r"(b[1]));
}
__device__ __forceinline__ void mma2(float* d, const uint32_t* a, uint32_t b0, uint32_t b1) {
    asm volatile("mma.sync.aligned.m16n8k16.row.col.f32.bf16.bf16.f32 "
        "{%0,%1,%2,%3}, {%4,%5,%6,%7}, {%8,%9}, {%0,%1,%2,%3};"
        : "+f"(d[0]), "+f"(d[1]), "+f"(d[2]), "+f"(d[3])
        : "r"(a[0]), "r"(a[1]), "r"(a[2]), "r"(a[3]), "r"(b0), "r"(b1));
}

__device__ __forceinline__ uint32_t pack_split2(float a, float b, uint32_t& lo_out) {
    __nv_bfloat16 ha = __float2bfloat16(a), hb = __float2bfloat16(b);
    __nv_bfloat16 la = __float2bfloat16(a - __bfloat162float(ha));
    __nv_bfloat16 lb = __float2bfloat16(b - __bfloat162float(hb));
    __nv_bfloat162 H(ha, hb), L(la, lb);
    lo_out = *(uint32_t*)&L;
    return *(uint32_t*)&H;
}

// ---------------------------------------------------------------------------
// Split fp32 -> bf16 hi/lo (row-major, elementwise)
// ---------------------------------------------------------------------------
__global__ __launch_bounds__(256) void split_rm(
    const float4* __restrict__ in, __nv_bfloat16* __restrict__ hi,
    __nv_bfloat16* __restrict__ lo, int n4)
{
    int i = blockIdx.x * 256 + threadIdx.x;
    if (i >= n4) return;
    float4 v = in[i];
    uint32_t l0, l1;
    uint32_t h0 = pack_split2(v.x, v.y, l0);
    uint32_t h1 = pack_split2(v.z, v.w, l1);
    uint32_t* H = (uint32_t*)hi;
    uint32_t* L = (uint32_t*)lo;
    H[2*i] = h0; H[2*i+1] = h1;
    L[2*i] = l0; L[2*i+1] = l1;
}

// ---------------------------------------------------------------------------
// Transpose + split: W[K,N] fp32 -> WT_hi[N,K], WT_lo[N,K] bf16
// ---------------------------------------------------------------------------
__global__ __launch_bounds__(256) void transpose_split(
    const float* __restrict__ W, __nv_bfloat16* __restrict__ Thi,
    __nv_bfloat16* __restrict__ Tlo, int K, int N)
{
    __shared__ float t[32][33];
    int tx = threadIdx.x & 31, ty = threadIdx.x >> 5;   // 32x8
    int n0 = blockIdx.x * 32, k0 = blockIdx.y * 32;
    #pragma unroll
    for (int i = 0; i < 32; i += 8)
        t[ty + i][tx] = W[(size_t)(k0 + ty + i) * N + n0 + tx];
    __syncthreads();
    #pragma unroll
    for (int i = 0; i < 32; i += 8) {
        float v = t[tx][ty + i];
        __nv_bfloat16 h = __float2bfloat16(v);
        __nv_bfloat16 l = __float2bfloat16(v - __bfloat162float(h));
        size_t o = (size_t)(n0 + ty + i) * K + k0 + tx;
        Thi[o] = h; Tlo[o] = l;
    }
}

// ---------------------------------------------------------------------------
// HMMA GEMM: C = A @ Bt^T, A/Bt bf16 hi/lo; 3 passes. Output fp32 (Cf) or
// fused-split bf16 hi/lo (Chi/Clo) when Cf == nullptr.
// CTA 128x128, 8 warps (32x64), BK=64, cp.async 3-STAGE pipeline, rows pad 72.
// ---------------------------------------------------------------------------
#define BKp 72
#define TILE_B (128 * BKp * 2)
#define STAGE_B (4 * TILE_B)               // 73728
#define GEMM_SMEM (3 * STAGE_B)            // 221184

__global__ __launch_bounds__(256, 1)
void gemm_hmma(const __nv_bfloat16* __restrict__ Ahi,
               const __nv_bfloat16* __restrict__ Alo,
               const __nv_bfloat16* __restrict__ Bhi,
               const __nv_bfloat16* __restrict__ Blo,
               float* __restrict__ Cf,
               __nv_bfloat16* __restrict__ Chi, __nv_bfloat16* __restrict__ Clo,
               int M, int N, int K)
{
    extern __shared__ char smem[];
    const uint32_t sb = smem_u32(smem);
    const int tid = threadIdx.x;
    const int m0 = blockIdx.y * 128, n0 = blockIdx.x * 128;
    const int l = tid & 31, w = tid >> 5;
    const int wm = (w & 3) * 32, wn = (w >> 2) * 64;
    const int NCH = K >> 6;

    float acc[2][8][4];
    #pragma unroll
    for (int mt = 0; mt < 2; mt++)
        #pragma unroll
        for (int nt = 0; nt < 8; nt++)
            #pragma unroll
            for (int e = 0; e < 4; e++) acc[mt][nt][e] = 0.0f;

    const __nv_bfloat16* srcs[4] = {Ahi, Alo, Bhi, Blo};

    // prologue: chunks 0 and 1 into stages 0, 1 (NCH >= 16 always here)
    #pragma unroll
    for (int pc = 0; pc < 2; pc++) {
        #pragma unroll
        for (int a = 0; a < 4; a++) {
            const __nv_bfloat16* src = srcs[a];
            const int rb = (a < 2) ? m0 : n0;
            #pragma unroll
            for (int it = 0; it < 4; it++) {
                int i = tid + it * 256;
                int r = i >> 3, s = i & 7;
                CP_ASYNC16(sb + pc * STAGE_B + a * TILE_B + (r * BKp + s * 8) * 2,
                           src + (size_t)(rb + r) * K + (pc << 6) + (s << 3));
            }
        }
        CP_COMMIT();
    }

    for (int c = 0; c < NCH; c++) {
        if (c + 2 < NCH) {
            const uint32_t st = ((c + 2) % 3) * STAGE_B;
            #pragma unroll
            for (int a = 0; a < 4; a++) {
                const __nv_bfloat16* src = srcs[a];
                const int rb = (a < 2) ? m0 : n0;
                #pragma unroll
                for (int it = 0; it < 4; it++) {
                    int i = tid + it * 256;
                    int r = i >> 3, s = i & 7;
                    CP_ASYNC16(sb + st + a * TILE_B + (r * BKp + s * 8) * 2,
                               src + (size_t)(rb + r) * K + ((c + 2) << 6) + (s << 3));
                }
            }
            CP_COMMIT();
            CP_WAIT2();
        } else if (c + 1 < NCH) {
            CP_WAIT1();
        } else {
            CP_WAIT0();
        }
        __syncthreads();

        const uint32_t sbase = sb + (c % 3) * STAGE_B;
        #pragma unroll
        for (int pass = 0; pass < 3; pass++) {
            const uint32_t aoff = sbase + (pass == 2 ? TILE_B : 0);
            const uint32_t boff = sbase + (pass == 1 ? 3 * TILE_B : 2 * TILE_B);
            #pragma unroll
            for (int kb = 0; kb < 64; kb += 16) {
                uint32_t af[2][4], bf[8][2];
                #pragma unroll
                for (int mt = 0; mt < 2; mt++) {
                    int row = wm + mt * 16 + (l & 15);
                    int col = kb + ((l & 16) >> 1);
                    ldsm4(af[mt], aoff + (row * BKp + col) * 2);
                }
                #pragma unroll
                for (int nt2 = 0; nt2 < 4; nt2++) {
                    int row = wn + nt2 * 16 + (l & 7) + ((l & 16) >> 1);
                    int col = kb + (l & 8);
                    uint32_t r4[4];
                    ldsm4(r4, boff + (row * BKp + col) * 2);
                    bf[nt2 * 2][0] = r4[0];  bf[nt2 * 2][1] = r4[1];
                    bf[nt2 * 2 + 1][0] = r4[2];  bf[nt2 * 2 + 1][1] = r4[3];
                }
                #pragma unroll
                for (int mt = 0; mt < 2; mt++)
                    #pragma unroll
                    for (int nt = 0; nt < 8; nt++)
                        mma16816(acc[mt][nt], af[mt], bf[nt]);
            }
        }
        __syncthreads();
    }

    #pragma unroll
    for (int mt = 0; mt < 2; mt++) {
        int row = m0 + wm + mt * 16 + (l >> 2);
        #pragma unroll
        for (int nt = 0; nt < 8; nt++) {
            int col = n0 + wn + nt * 8 + (l & 3) * 2;
            if (Cf) {
                *(float2*)&Cf[(size_t)row * N + col] =
                    make_float2(acc[mt][nt][0], acc[mt][nt][1]);
                *(float2*)&Cf[(size_t)(row + 8) * N + col] =
                    make_float2(acc[mt][nt][2], acc[mt][nt][3]);
            } else {
                uint32_t lo;
                uint32_t hi = pack_split2(acc[mt][nt][0], acc[mt][nt][1], lo);
                *(uint32_t*)&Chi[(size_t)row * N + col] = hi;
                *(uint32_t*)&Clo[(size_t)row * N + col] = lo;
                hi = pack_split2(acc[mt][nt][2], acc[mt][nt][3], lo);
                *(uint32_t*)&Chi[(size_t)(row + 8) * N + col] = hi;
                *(uint32_t*)&Clo[(size_t)(row + 8) * N + col] = lo;
            }
        }
    }
}

// ---------------------------------------------------------------------------
// HMMA flash attention: BQ=128 q/CTA (8 warps x 16), BKV=64, d=128 resident.
// Pass-major MMA ordering: accumulator reuse distance 8 (was 1).
// ---------------------------------------------------------------------------
#define BQ2 128
#define BKV2 64
#define SQel 136
#define F_QHI 0
#define F_QLO 34816
#define F_STAGE0 69632
#define F_STAGE_SZ 69632
#define FLASH2_SMEM (F_STAGE0 + 2 * F_STAGE_SZ)   // 208896 B

__global__ __launch_bounds__(256, 1)
void flash_hmma(const __nv_bfloat16* __restrict__ Qhi, const __nv_bfloat16* __restrict__ Qlo,
                const __nv_bfloat16* __restrict__ Khi, const __nv_bfloat16* __restrict__ Klo,
                const __nv_bfloat16* __restrict__ Vhi, const __nv_bfloat16* __restrict__ Vlo,
                __nv_bfloat16* __restrict__ Ahi, __nv_bfloat16* __restrict__ Alo)
{
    extern __shared__ char smem[];
    const uint32_t sb = smem_u32(smem);
    const int qb = blockIdx.x, h = blockIdx.y, b = blockIdx.z;
    const int kvh = h >> 2;
    const int tid = threadIdx.x;
    const int l = tid & 31, w = tid >> 5;
    const int wq = w * 16;
    const float scale = 0.08838834764831845f;

    #pragma unroll
    for (int it = 0; it < 16; it++) {
        int idx = tid + it * 256;
        int t = idx >> 11, r = (idx >> 4) & 127, s = idx & 15;
        const __nv_bfloat16* src = t ? Qlo : Qhi;
        size_t grow = ((size_t)(b * SEQ + qb * BQ2 + r) * HQ + h) * HD;
        CP_ASYNC16(sb + (t ? F_QLO : F_QHI) + (r * SQel + s * 8) * 2, src + grow + s * 8);
    }
    const __nv_bfloat16* kvsrc[4] = {Khi, Klo, Vhi, Vlo};
    #pragma unroll
    for (int it = 0; it < 16; it++) {
        int idx = tid + it * 256;
        int t = idx >> 10, r = (idx >> 4) & 63, s = idx & 15;
        size_t grow = ((size_t)(b * SEQ + r) * HKV + kvh) * HD;
        CP_ASYNC16(sb + F_STAGE0 + t * 17408 + (r * SQel + s * 8) * 2, kvsrc[t] + grow + s * 8);
    }
    CP_COMMIT();

    float oacc[16][4];
    #pragma unroll
    for (int nt = 0; nt < 16; nt++)
        #pragma unroll
        for (int e = 0; e < 4; e++) oacc[nt][e] = 0.0f;
    float m0 = -1e30f, m1 = -1e30f, lsum0 = 0.0f, lsum1 = 0.0f;
    const int qg0 = qb * BQ2 + wq + (l >> 2);

    const int niter = 2 * (qb + 1);
    for (int kt = 0; kt < niter; kt++) {
        if (kt + 1 < niter) {
            uint32_t st = sb + F_STAGE0 + ((kt + 1) & 1) * F_STAGE_SZ;
            #pragma unroll
            for (int it = 0; it < 16; it++) {
                int idx = tid + it * 256;
                int t = idx >> 10, r = (idx >> 4) & 63, s = idx & 15;
                size_t grow = ((size_t)(b * SEQ + (kt + 1) * BKV2 + r) * HKV + kvh) * HD;
                CP_ASYNC16(st + t * 17408 + (r * SQel + s * 8) * 2, kvsrc[t] + grow + s * 8);
            }
            CP_COMMIT();
            CP_WAIT1();
        } else {
            CP_WAIT0();
        }
        __syncthreads();
        const uint32_t kb = sb + F_STAGE0 + (kt & 1) * F_STAGE_SZ;

        // ---- S = Q.K^T, pass-major (reuse distance 8)
        float sacc[8][4];
        #pragma unroll
        for (int nt = 0; nt < 8; nt++)
            #pragma unroll
            for (int e = 0; e < 4; e++) sacc[nt][e] = 0.0f;

        #pragma unroll
        for (int ks = 0; ks < 8; ks++) {
            uint32_t ahi[4], alo[4];
            uint32_t aaddr = ((wq + (l & 15)) * SQel + ks * 16 + ((l & 16) >> 1)) * 2;
            ldsm4(ahi, sb + F_QHI + aaddr);
            ldsm4(alo, sb + F_QLO + aaddr);
            uint32_t bhi[8][2], blo[8][2];
            #pragma unroll
            for (int nt2 = 0; nt2 < 4; nt2++) {
                int row = nt2 * 16 + (l & 7) + ((l & 16) >> 1);
                int col = ks * 16 + (l & 8);
                uint32_t r4[4];
                ldsm4(r4, kb + (row * SQel + col) * 2);
                bhi[nt2*2][0] = r4[0]; bhi[nt2*2][1] = r4[1];
                bhi[nt2*2+1][0] = r4[2]; bhi[nt2*2+1][1] = r4[3];
                ldsm4(r4, kb + 17408 + (row * SQel + col) * 2);
                blo[nt2*2][0] = r4[0]; blo[nt2*2][1] = r4[1];
                blo[nt2*2+1][0] = r4[2]; blo[nt2*2+1][1] = r4[3];
            }
            #pragma unroll
            for (int nt = 0; nt < 8; nt++) mma16816(sacc[nt], ahi, bhi[nt]);
            #pragma unroll
            for (int nt = 0; nt < 8; nt++) mma16816(sacc[nt], ahi, blo[nt]);
            #pragma unroll
            for (int nt = 0; nt < 8; nt++) mma16816(sacc[nt], alo, bhi[nt]);
        }

        // ---- softmax (fp32, fragment-level)
        const bool domask = (kt >= 2 * qb);
        #pragma unroll
        for (int nt = 0; nt < 8; nt++)
            #pragma unroll
            for (int e = 0; e < 4; e++) {
                float s = sacc[nt][e] * scale;
                if (domask) {
                    int kg = kt * BKV2 + nt * 8 + (l & 3) * 2 + (e & 1);
                    int qg = qg0 + ((e >= 2) ? 8 : 0);
                    if (kg > qg) s = -1e30f;
                }
                sacc[nt][e] = s;
            }
        float mx0 = -1e30f, mx1 = -1e30f;
        #pragma unroll
        for (int nt = 0; nt < 8; nt++) {
            mx0 = fmaxf(mx0, fmaxf(sacc[nt][0], sacc[nt][1]));
            mx1 = fmaxf(mx1, fmaxf(sacc[nt][2], sacc[nt][3]));
        }
        mx0 = fmaxf(mx0, __shfl_xor_sync(0xffffffffu, mx0, 1));
        mx0 = fmaxf(mx0, __shfl_xor_sync(0xffffffffu, mx0, 2));
        mx1 = fmaxf(mx1, __shfl_xor_sync(0xffffffffu, mx1, 1));
        mx1 = fmaxf(mx1, __shfl_xor_sync(0xffffffffu, mx1, 2));
        float mn0 = fmaxf(m0, mx0), mn1 = fmaxf(m1, mx1);
        float c0 = __expf(m0 - mn0), c1 = __expf(m1 - mn1);
        m0 = mn0; m1 = mn1;
        float ps0 = 0.0f, ps1 = 0.0f;
        #pragma unroll
        for (int nt = 0; nt < 8; nt++) {
            float p0 = __expf(sacc[nt][0] - mn0), p1 = __expf(sacc[nt][1] - mn0);
            float p2 = __expf(sacc[nt][2] - mn1), p3 = __expf(sacc[nt][3] - mn1);
            ps0 += p0 + p1; ps1 += p2 + p3;
            sacc[nt][0] = p0; sacc[nt][1] = p1; sacc[nt][2] = p2; sacc[nt][3] = p3;
        }
        ps0 += __shfl_xor_sync(0xffffffffu, ps0, 1);
        ps0 += __shfl_xor_sync(0xffffffffu, ps0, 2);
        ps1 += __shfl_xor_sync(0xffffffffu, ps1, 1);
        ps1 += __shfl_xor_sync(0xffffffffu, ps1, 2);
        lsum0 = lsum0 * c0 + ps0;
        lsum1 = lsum1 * c1 + ps1;
        #pragma unroll
        for (int nt = 0; nt < 16; nt++) {
            oacc[nt][0] *= c0; oacc[nt][1] *= c0;
            oacc[nt][2] *= c1; oacc[nt][3] *= c1;
        }

        // ---- O += P.V, pass-major over cached half-tiles (reuse distance 8)
        #pragma unroll
        for (int j = 0; j < 4; j++) {
            uint32_t phi[4], plo[4];
            phi[0] = pack_split2(sacc[2*j][0],   sacc[2*j][1],   plo[0]);
            phi[1] = pack_split2(sacc[2*j][2],   sacc[2*j][3],   plo[1]);
            phi[2] = pack_split2(sacc[2*j+1][0], sacc[2*j+1][1], plo[2]);
            phi[3] = pack_split2(sacc[2*j+1][2], sacc[2*j+1][3], plo[3]);
            #pragma unroll
            for (int half = 0; half < 2; half++) {
                uint32_t vh[4][4], vl[4][4];
                #pragma unroll
                for (int q4 = 0; q4 < 4; q4++) {
                    int np = half * 4 + q4;
                    uint32_t vaddr = ((j * 16 + (l & 15)) * SQel + np * 16 + ((l & 16) >> 1)) * 2;
                    ldsm4t(vh[q4], kb + 34816 + vaddr);
                    ldsm4t(vl[q4], kb + 52224 + vaddr);
                }
                #pragma unroll
                for (int q4 = 0; q4 < 4; q4++) {
                    int np = half * 4 + q4;
                    mma2(oacc[2*np],   phi, vh[q4][0], vh[q4][1]);
                    mma2(oacc[2*np+1], phi, vh[q4][2], vh[q4][3]);
                }
                #pragma unroll
                for (int q4 = 0; q4 < 4; q4++) {
                    int np = half * 4 + q4;
                    mma2(oacc[2*np],   phi, vl[q4][0], vl[q4][1]);
                    mma2(oacc[2*np+1], phi, vl[q4][2], vl[q4][3]);
                }
                #pragma unroll
                for (int q4 = 0; q4 < 4; q4++) {
                    int np = half * 4 + q4;
                    mma2(oacc[2*np],   plo, vh[q4][0], vh[q4][1]);
                    mma2(oacc[2*np+1], plo, vh[q4][2], vh[q4][3]);
                }
            }
        }
        __syncthreads();
    }

    float inv0 = 1.0f / lsum0, inv1 = 1.0f / lsum1;
    size_t base0 = ((size_t)(b * SEQ + qg0) * HQ + h) * HD;
    size_t base1 = base0 + (size_t)8 * HQ * HD;
    #pragma unroll
    for (int nt = 0; nt < 16; nt++) {
        int col = nt * 8 + (l & 3) * 2;
        uint32_t lo;
        uint32_t hi = pack_split2(oacc[nt][0] * inv0, oacc[nt][1] * inv0, lo);
        *(uint32_t*)&Ahi[base0 + col] = hi;
        *(uint32_t*)&Alo[base0 + col] = lo;
        hi = pack_split2(oacc[nt][2] * inv1, oacc[nt][3] * inv1, lo);
        *(uint32_t*)&Ahi[base1 + col] = hi;
        *(uint32_t*)&Alo[base1 + col] = lo;
    }
}

// ---------------------------------------------------------------------------
extern "C" void kernel_launch(void* const* d_in, const int* in_sizes, int n_in,
                              void* d_out, int out_size)
{
    const float* x  = (const float*)d_in[0];
    const float* wq = (const float*)d_in[1];
    const float* wk = (const float*)d_in[2];
    const float* wv = (const float*)d_in[3];
    const float* wo = (const float*)d_in[4];
    float* out = (float*)d_out;

    __nv_bfloat16 *xhi, *xlo, *qhi, *qlo, *khi, *klo, *vhi, *vlo, *ahi, *alo;
    __nv_bfloat16 *wqThi, *wqTlo, *wkThi, *wkTlo, *wvThi, *wvTlo, *woThi, *woTlo;
    cudaGetSymbolAddress((void**)&xhi, g_xhi);
    cudaGetSymbolAddress((void**)&xlo, g_xlo);
    cudaGetSymbolAddress((void**)&qhi, g_qhi);
    cudaGetSymbolAddress((void**)&qlo, g_qlo);
    cudaGetSymbolAddress((void**)&khi, g_khi);
    cudaGetSymbolAddress((void**)&klo, g_klo);
    cudaGetSymbolAddress((void**)&vhi, g_vhi);
    cudaGetSymbolAddress((void**)&vlo, g_vlo);
    cudaGetSymbolAddress((void**)&ahi, g_ahi);
    cudaGetSymbolAddress((void**)&alo, g_alo);
    cudaGetSymbolAddress((void**)&wqThi, g_wqThi);
    cudaGetSymbolAddress((void**)&wqTlo, g_wqTlo);
    cudaGetSymbolAddress((void**)&wkThi, g_wkThi);
    cudaGetSymbolAddress((void**)&wkTlo, g_wkTlo);
    cudaGetSymbolAddress((void**)&wvThi, g_wvThi);
    cudaGetSymbolAddress((void**)&wvTlo, g_wvTlo);
    cudaGetSymbolAddress((void**)&woThi, g_woThi);
    cudaGetSymbolAddress((void**)&woTlo, g_woTlo);

    cudaFuncSetAttribute(gemm_hmma, cudaFuncAttributeMaxDynamicSharedMemorySize,
                         GEMM_SMEM);
    cudaFuncSetAttribute(flash_hmma, cudaFuncAttributeMaxDynamicSharedMemorySize,
                         FLASH2_SMEM);

    const int n4 = ROWS * DIMV / 4;

    split_rm<<<n4 / 256, 256>>>((const float4*)x, xhi, xlo, n4);
    transpose_split<<<dim3(DIMV / 32,  DIMV / 32), 256>>>(wq, wqThi, wqTlo, DIMV, DIMV);
    transpose_split<<<dim3(KVDIM / 32, DIMV / 32), 256>>>(wk, wkThi, wkTlo, DIMV, KVDIM);
    transpose_split<<<dim3(KVDIM / 32, DIMV / 32), 256>>>(wv, wvThi, wvTlo, DIMV, KVDIM);
    transpose_split<<<dim3(DIMV / 32,  DIMV / 32), 256>>>(wo, woThi, woTlo, DIMV, DIMV);

    gemm_hmma<<<dim3(DIMV / 128,  ROWS / 128), 256, GEMM_SMEM>>>(
        xhi, xlo, wqThi, wqTlo, nullptr, qhi, qlo, ROWS, DIMV, DIMV);
    gemm_hmma<<<dim3(KVDIM / 128, ROWS / 128), 256, GEMM_SMEM>>>(
        xhi, xlo, wkThi, wkTlo, nullptr, khi, klo, ROWS, KVDIM, DIMV);
    gemm_hmma<<<dim3(KVDIM / 128, ROWS / 128), 256, GEMM_SMEM>>>(
        xhi, xlo, wvThi, wvTlo, nullptr, vhi, vlo, ROWS, KVDIM, DIMV);

    flash_hmma<<<dim3(SEQ / BQ2, HQ, BATCH), 256, FLASH2_SMEM>>>(
        qhi, qlo, khi, klo, vhi, vlo, ahi, alo);

    gemm_hmma<<<dim3(DIMV / 128, ROWS / 128), 256, GEMM_SMEM>>>(
        ahi, alo, woThi, woTlo, out, nullptr, nullptr, ROWS, DIMV, DIMV);
}

// round 11
// speedup vs baseline: 1.0154x; 1.0154x over previous
#include <cuda_runtime.h>
#include <cuda_bf16.h>
#include <cstdint>

// Problem constants
#define BATCH   2
#define SEQ     2048
#define DIMV    4096
#define HQ      32
#define HKV     8
#define HD      128
#define ROWS    (BATCH * SEQ)      // 4096
#define KVDIM   (HKV * HD)         // 1024

// ---------------------------------------------------------------------------
// Device scratch (allocation-free rule)
// ---------------------------------------------------------------------------
__device__ __nv_bfloat16 g_xhi[ROWS * DIMV],  g_xlo[ROWS * DIMV];
__device__ __nv_bfloat16 g_qhi[ROWS * DIMV],  g_qlo[ROWS * DIMV];
__device__ __nv_bfloat16 g_khi[ROWS * KVDIM], g_klo[ROWS * KVDIM];
__device__ __nv_bfloat16 g_vhi[ROWS * KVDIM], g_vlo[ROWS * KVDIM];
__device__ __nv_bfloat16 g_ahi[ROWS * DIMV],  g_alo[ROWS * DIMV];
__device__ __nv_bfloat16 g_wqThi[DIMV * DIMV],  g_wqTlo[DIMV * DIMV];
__device__ __nv_bfloat16 g_wkThi[KVDIM * DIMV], g_wkTlo[KVDIM * DIMV];
__device__ __nv_bfloat16 g_wvThi[KVDIM * DIMV], g_wvTlo[KVDIM * DIMV];
__device__ __nv_bfloat16 g_woThi[DIMV * DIMV],  g_woTlo[DIMV * DIMV];

// ---------------------------------------------------------------------------
// Arch-generic PTX helpers (NO 'a'-gated instructions: sm_103 virtual target)
// ---------------------------------------------------------------------------
__device__ __forceinline__ uint32_t smem_u32(const void* p) {
    uint32_t a;
    asm("{ .reg .u64 t; cvta.to.shared.u64 t, %1; cvt.u32.u64 %0, t; }"
        : "=r"(a) : "l"(p));
    return a;
}

#define CP_ASYNC16(saddr, gptr) \
    asm volatile("cp.async.cg.shared.global [%0], [%1], 16;" \
        :: "r"(saddr), "l"(gptr) : "memory")
#define CP_COMMIT()  asm volatile("cp.async.commit_group;" ::: "memory")
#define CP_WAIT1()   asm volatile("cp.async.wait_group 1;" ::: "memory")
#define CP_WAIT0()   asm volatile("cp.async.wait_group 0;" ::: "memory")

__device__ __forceinline__ void ldsm4(uint32_t* r, uint32_t addr) {
    asm volatile("ldmatrix.sync.aligned.m8n8.x4.shared.b16 {%0,%1,%2,%3}, [%4];"
        : "=r"(r[0]), "=r"(r[1]), "=r"(r[2]), "=r"(r[3]) : "r"(addr));
}
__device__ __forceinline__ void ldsm4t(uint32_t* r, uint32_t addr) {
    asm volatile("ldmatrix.sync.aligned.m8n8.x4.trans.shared.b16 {%0,%1,%2,%3}, [%4];"
        : "=r"(r[0]), "=r"(r[1]), "=r"(r[2]), "=r"(r[3]) : "r"(addr));
}

__device__ __forceinline__ void mma16816(float* d, const uint32_t* a, const uint32_t* b) {
    asm volatile("mma.sync.aligned.m16n8k16.row.col.f32.bf16.bf16.f32 "
        "{%0,%1,%2,%3}, {%4,%5,%6,%7}, {%8,%9}, {%0,%1,%2,%3};"
        : "+f"(d[0]), "+f"(d[1]), "+f"(d[2]), "+f"(d[3])
        : "r"(a[0]), "r"(a[1]), "r"(a[2]), "r"(a[3]), "r"(b[0]), "r"(b[1]));
}
__device__ __forceinline__ void mma2(float* d, const uint32_t* a, uint32_t b0, uint32_t b1) {
    asm volatile("mma.sync.aligned.m16n8k16.row.col.f32.bf16.bf16.f32 "
        "{%0,%1,%2,%3}, {%4,%5,%6,%7}, {%8,%9}, {%0,%1,%2,%3};"
        : "+f"(d[0]), "+f"(d[1]), "+f"(d[2]), "+f"(d[3])
        : "r"(a[0]), "r"(a[1]), "r"(a[2]), "r"(a[3]), "r"(b0), "r"(b1));
}

__device__ __forceinline__ uint32_t pack_split2(float a, float b, uint32_t& lo_out) {
    __nv_bfloat16 ha = __float2bfloat16(a), hb = __float2bfloat16(b);
    __nv_bfloat16 la = __float2bfloat16(a - __bfloat162float(ha));
    __nv_bfloat16 lb = __float2bfloat16(b - __bfloat162float(hb));
    __nv_bfloat162 H(ha, hb), L(la, lb);
    lo_out = *(uint32_t*)&L;
    return *(uint32_t*)&H;
}

// ---------------------------------------------------------------------------
// Split fp32 -> bf16 hi/lo (row-major, elementwise)
// ---------------------------------------------------------------------------
__global__ __launch_bounds__(256) void split_rm(
    const float4* __restrict__ in, __nv_bfloat16* __restrict__ hi,
    __nv_bfloat16* __restrict__ lo, int n4)
{
    int i = blockIdx.x * 256 + threadIdx.x;
    if (i >= n4) return;
    float4 v = in[i];
    uint32_t l0, l1;
    uint32_t h0 = pack_split2(v.x, v.y, l0);
    uint32_t h1 = pack_split2(v.z, v.w, l1);
    uint32_t* H = (uint32_t*)hi;
    uint32_t* L = (uint32_t*)lo;
    H[2*i] = h0; H[2*i+1] = h1;
    L[2*i] = l0; L[2*i+1] = l1;
}

// ---------------------------------------------------------------------------
// Transpose + split: W[K,N] fp32 -> WT_hi[N,K], WT_lo[N,K] bf16
// ---------------------------------------------------------------------------
__global__ __launch_bounds__(256) void transpose_split(
    const float* __restrict__ W, __nv_bfloat16* __restrict__ Thi,
    __nv_bfloat16* __restrict__ Tlo, int K, int N)
{
    __shared__ float t[32][33];
    int tx = threadIdx.x & 31, ty = threadIdx.x >> 5;   // 32x8
    int n0 = blockIdx.x * 32, k0 = blockIdx.y * 32;
    #pragma unroll
    for (int i = 0; i < 32; i += 8)
        t[ty + i][tx] = W[(size_t)(k0 + ty + i) * N + n0 + tx];
    __syncthreads();
    #pragma unroll
    for (int i = 0; i < 32; i += 8) {
        float v = t[tx][ty + i];
        __nv_bfloat16 h = __float2bfloat16(v);
        __nv_bfloat16 l = __float2bfloat16(v - __bfloat162float(h));
        size_t o = (size_t)(n0 + ty + i) * K + k0 + tx;
        Thi[o] = h; Tlo[o] = l;
    }
}

// ---------------------------------------------------------------------------
// HMMA GEMM: C = A @ Bt^T, A/Bt bf16 hi/lo; 3 passes. Output fp32 (Cf) or
// fused-split bf16 hi/lo (Chi/Clo) when Cf == nullptr.
// CTA tile 128x128, 8 warps (32x64). NEW: BK=32, pad 40 (80B rows,
// conflict-free ldsm bank walk), 2 stages x 40960B = 81920B/CTA
// -> 2 CTAs/SM (16 warps/SM) to fill sync/epilogue bubbles.
// ---------------------------------------------------------------------------
#define BK2 32
#define BKp2 40
#define TILE2_B (128 * BKp2 * 2)            // 10240
#define STAGE2_B (4 * TILE2_B)              // 40960
#define GEMM_SMEM (2 * STAGE2_B)            // 81920

__global__ __launch_bounds__(256, 2)
void gemm_hmma(const __nv_bfloat16* __restrict__ Ahi,
               const __nv_bfloat16* __restrict__ Alo,
               const __nv_bfloat16* __restrict__ Bhi,
               const __nv_bfloat16* __restrict__ Blo,
               float* __restrict__ Cf,
               __nv_bfloat16* __restrict__ Chi, __nv_bfloat16* __restrict__ Clo,
               int M, int N, int K)
{
    extern __shared__ char smem[];
    const uint32_t sb = smem_u32(smem);
    const int tid = threadIdx.x;
    const int m0 = blockIdx.y * 128, n0 = blockIdx.x * 128;
    const int l = tid & 31, w = tid >> 5;
    const int wm = (w & 3) * 32, wn = (w >> 2) * 64;
    const int NCH = K / BK2;

    float acc[2][8][4];
    #pragma unroll
    for (int mt = 0; mt < 2; mt++)
        #pragma unroll
        for (int nt = 0; nt < 8; nt++)
            #pragma unroll
            for (int e = 0; e < 4; e++) acc[mt][nt][e] = 0.0f;

    const __nv_bfloat16* srcs[4] = {Ahi, Alo, Bhi, Blo};

    // prologue: chunk 0 into stage 0.
    // 4 arrays x 128 rows x 4 segs(16B) = 2048 segs -> 8 per thread
    #pragma unroll
    for (int it = 0; it < 8; it++) {
        int i = tid + it * 256;
        int a = i >> 9, j = i & 511;
        int r = j >> 2, s = j & 3;
        const int rb = (a < 2) ? m0 : n0;
        CP_ASYNC16(sb + a * TILE2_B + (r * BKp2 + s * 8) * 2,
                   srcs[a] + (size_t)(rb + r) * K + (s << 3));
    }
    CP_COMMIT();

    for (int c = 0; c < NCH; c++) {
        if (c + 1 < NCH) {
            const uint32_t st = ((c + 1) & 1) * STAGE2_B;
            #pragma unroll
            for (int it = 0; it < 8; it++) {
                int i = tid + it * 256;
                int a = i >> 9, j = i & 511;
                int r = j >> 2, s = j & 3;
                const int rb = (a < 2) ? m0 : n0;
                CP_ASYNC16(sb + st + a * TILE2_B + (r * BKp2 + s * 8) * 2,
                           srcs[a] + (size_t)(rb + r) * K + (c + 1) * BK2 + (s << 3));
            }
            CP_COMMIT();
            CP_WAIT1();
        } else {
            CP_WAIT0();
        }
        __syncthreads();

        const uint32_t sbase = sb + (c & 1) * STAGE2_B;
        #pragma unroll
        for (int pass = 0; pass < 3; pass++) {
            const uint32_t aoff = sbase + (pass == 2 ? TILE2_B : 0);
            const uint32_t boff = sbase + (pass == 1 ? 3 * TILE2_B : 2 * TILE2_B);
            #pragma unroll
            for (int kb = 0; kb < BK2; kb += 16) {
                uint32_t af[2][4], bf[8][2];
                #pragma unroll
                for (int mt = 0; mt < 2; mt++) {
                    int row = wm + mt * 16 + (l & 15);
                    int col = kb + ((l & 16) >> 1);
                    ldsm4(af[mt], aoff + (row * BKp2 + col) * 2);
                }
                #pragma unroll
                for (int nt2 = 0; nt2 < 4; nt2++) {
                    int row = wn + nt2 * 16 + (l & 7) + ((l & 16) >> 1);
                    int col = kb + (l & 8);
                    uint32_t r4[4];
                    ldsm4(r4, boff + (row * BKp2 + col) * 2);
                    bf[nt2 * 2][0] = r4[0];  bf[nt2 * 2][1] = r4[1];
                    bf[nt2 * 2 + 1][0] = r4[2];  bf[nt2 * 2 + 1][1] = r4[3];
                }
                #pragma unroll
                for (int mt = 0; mt < 2; mt++)
                    #pragma unroll
                    for (int nt = 0; nt < 8; nt++)
                        mma16816(acc[mt][nt], af[mt], bf[nt]);
            }
        }
        __syncthreads();
    }

    #pragma unroll
    for (int mt = 0; mt < 2; mt++) {
        int row = m0 + wm + mt * 16 + (l >> 2);
        #pragma unroll
        for (int nt = 0; nt < 8; nt++) {
            int col = n0 + wn + nt * 8 + (l & 3) * 2;
            if (Cf) {
                *(float2*)&Cf[(size_t)row * N + col] =
                    make_float2(acc[mt][nt][0], acc[mt][nt][1]);
                *(float2*)&Cf[(size_t)(row + 8) * N + col] =
                    make_float2(acc[mt][nt][2], acc[mt][nt][3]);
            } else {
                uint32_t lo;
                uint32_t hi = pack_split2(acc[mt][nt][0], acc[mt][nt][1], lo);
                *(uint32_t*)&Chi[(size_t)row * N + col] = hi;
                *(uint32_t*)&Clo[(size_t)row * N + col] = lo;
                hi = pack_split2(acc[mt][nt][2], acc[mt][nt][3], lo);
                *(uint32_t*)&Chi[(size_t)(row + 8) * N + col] = hi;
                *(uint32_t*)&Clo[(size_t)(row + 8) * N + col] = lo;
            }
        }
    }
}

// ---------------------------------------------------------------------------
// HMMA flash attention: unchanged from R9 (measured equal to R8 within noise).
// ---------------------------------------------------------------------------
#define BQ2 128
#define BKV2 64
#define SQel 136
#define F_QHI 0
#define F_QLO 34816
#define F_STAGE0 69632
#define F_STAGE_SZ 69632
#define FLASH2_SMEM (F_STAGE0 + 2 * F_STAGE_SZ)   // 208896 B

__global__ __launch_bounds__(256, 1)
void flash_hmma(const __nv_bfloat16* __restrict__ Qhi, const __nv_bfloat16* __restrict__ Qlo,
                const __nv_bfloat16* __restrict__ Khi, const __nv_bfloat16* __restrict__ Klo,
                const __nv_bfloat16* __restrict__ Vhi, const __nv_bfloat16* __restrict__ Vlo,
                __nv_bfloat16* __restrict__ Ahi, __nv_bfloat16* __restrict__ Alo)
{
    extern __shared__ char smem[];
    const uint32_t sb = smem_u32(smem);
    const int qb = blockIdx.x, h = blockIdx.y, b = blockIdx.z;
    const int kvh = h >> 2;
    const int tid = threadIdx.x;
    const int l = tid & 31, w = tid >> 5;
    const int wq = w * 16;
    const float scale = 0.08838834764831845f;

    #pragma unroll
    for (int it = 0; it < 16; it++) {
        int idx = tid + it * 256;
        int t = idx >> 11, r = (idx >> 4) & 127, s = idx & 15;
        const __nv_bfloat16* src = t ? Qlo : Qhi;
        size_t grow = ((size_t)(b * SEQ + qb * BQ2 + r) * HQ + h) * HD;
        CP_ASYNC16(sb + (t ? F_QLO : F_QHI) + (r * SQel + s * 8) * 2, src + grow + s * 8);
    }
    const __nv_bfloat16* kvsrc[4] = {Khi, Klo, Vhi, Vlo};
    #pragma unroll
    for (int it = 0; it < 16; it++) {
        int idx = tid + it * 256;
        int t = idx >> 10, r = (idx >> 4) & 63, s = idx & 15;
        size_t grow = ((size_t)(b * SEQ + r) * HKV + kvh) * HD;
        CP_ASYNC16(sb + F_STAGE0 + t * 17408 + (r * SQel + s * 8) * 2, kvsrc[t] + grow + s * 8);
    }
    CP_COMMIT();

    float oacc[16][4];
    #pragma unroll
    for (int nt = 0; nt < 16; nt++)
        #pragma unroll
        for (int e = 0; e < 4; e++) oacc[nt][e] = 0.0f;
    float m0 = -1e30f, m1 = -1e30f, lsum0 = 0.0f, lsum1 = 0.0f;
    const int qg0 = qb * BQ2 + wq + (l >> 2);

    const int niter = 2 * (qb + 1);
    for (int kt = 0; kt < niter; kt++) {
        if (kt + 1 < niter) {
            uint32_t st = sb + F_STAGE0 + ((kt + 1) & 1) * F_STAGE_SZ;
            #pragma unroll
            for (int it = 0; it < 16; it++) {
                int idx = tid + it * 256;
                int t = idx >> 10, r = (idx >> 4) & 63, s = idx & 15;
                size_t grow = ((size_t)(b * SEQ + (kt + 1) * BKV2 + r) * HKV + kvh) * HD;
                CP_ASYNC16(st + t * 17408 + (r * SQel + s * 8) * 2, kvsrc[t] + grow + s * 8);
            }
            CP_COMMIT();
            CP_WAIT1();
        } else {
            CP_WAIT0();
        }
        __syncthreads();
        const uint32_t kb = sb + F_STAGE0 + (kt & 1) * F_STAGE_SZ;

        float sacc[8][4];
        #pragma unroll
        for (int nt = 0; nt < 8; nt++)
            #pragma unroll
            for (int e = 0; e < 4; e++) sacc[nt][e] = 0.0f;

        #pragma unroll
        for (int ks = 0; ks < 8; ks++) {
            uint32_t ahi[4], alo[4];
            uint32_t aaddr = ((wq + (l & 15)) * SQel + ks * 16 + ((l & 16) >> 1)) * 2;
            ldsm4(ahi, sb + F_QHI + aaddr);
            ldsm4(alo, sb + F_QLO + aaddr);
            uint32_t bhi[8][2], blo[8][2];
            #pragma unroll
            for (int nt2 = 0; nt2 < 4; nt2++) {
                int row = nt2 * 16 + (l & 7) + ((l & 16) >> 1);
                int col = ks * 16 + (l & 8);
                uint32_t r4[4];
                ldsm4(r4, kb + (row * SQel + col) * 2);
                bhi[nt2*2][0] = r4[0]; bhi[nt2*2][1] = r4[1];
                bhi[nt2*2+1][0] = r4[2]; bhi[nt2*2+1][1] = r4[3];
                ldsm4(r4, kb + 17408 + (row * SQel + col) * 2);
                blo[nt2*2][0] = r4[0]; blo[nt2*2][1] = r4[1];
                blo[nt2*2+1][0] = r4[2]; blo[nt2*2+1][1] = r4[3];
            }
            #pragma unroll
            for (int nt = 0; nt < 8; nt++) mma16816(sacc[nt], ahi, bhi[nt]);
            #pragma unroll
            for (int nt = 0; nt < 8; nt++) mma16816(sacc[nt], ahi, blo[nt]);
            #pragma unroll
            for (int nt = 0; nt < 8; nt++) mma16816(sacc[nt], alo, bhi[nt]);
        }

        const bool domask = (kt >= 2 * qb);
        #pragma unroll
        for (int nt = 0; nt < 8; nt++)
            #pragma unroll
            for (int e = 0; e < 4; e++) {
                float s = sacc[nt][e] * scale;
                if (domask) {
                    int kg = kt * BKV2 + nt * 8 + (l & 3) * 2 + (e & 1);
                    int qg = qg0 + ((e >= 2) ? 8 : 0);
                    if (kg > qg) s = -1e30f;
                }
                sacc[nt][e] = s;
            }
        float mx0 = -1e30f, mx1 = -1e30f;
        #pragma unroll
        for (int nt = 0; nt < 8; nt++) {
            mx0 = fmaxf(mx0, fmaxf(sacc[nt][0], sacc[nt][1]));
            mx1 = fmaxf(mx1, fmaxf(sacc[nt][2], sacc[nt][3]));
        }
        mx0 = fmaxf(mx0, __shfl_xor_sync(0xffffffffu, mx0, 1));
        mx0 = fmaxf(mx0, __shfl_xor_sync(0xffffffffu, mx0, 2));
        mx1 = fmaxf(mx1, __shfl_xor_sync(0xffffffffu, mx1, 1));
        mx1 = fmaxf(mx1, __shfl_xor_sync(0xffffffffu, mx1, 2));
        float mn0 = fmaxf(m0, mx0), mn1 = fmaxf(m1, mx1);
        float c0 = __expf(m0 - mn0), c1 = __expf(m1 - mn1);
        m0 = mn0; m1 = mn1;
        float ps0 = 0.0f, ps1 = 0.0f;
        #pragma unroll
        for (int nt = 0; nt < 8; nt++) {
            float p0 = __expf(sacc[nt][0] - mn0), p1 = __expf(sacc[nt][1] - mn0);
            float p2 = __expf(sacc[nt][2] - mn1), p3 = __expf(sacc[nt][3] - mn1);
            ps0 += p0 + p1; ps1 += p2 + p3;
            sacc[nt][0] = p0; sacc[nt][1] = p1; sacc[nt][2] = p2; sacc[nt][3] = p3;
        }
        ps0 += __shfl_xor_sync(0xffffffffu, ps0, 1);
        ps0 += __shfl_xor_sync(0xffffffffu, ps0, 2);
        ps1 += __shfl_xor_sync(0xffffffffu, ps1, 1);
        ps1 += __shfl_xor_sync(0xffffffffu, ps1, 2);
        lsum0 = lsum0 * c0 + ps0;
        lsum1 = lsum1 * c1 + ps1;
        #pragma unroll
        for (int nt = 0; nt < 16; nt++) {
            oacc[nt][0] *= c0; oacc[nt][1] *= c0;
            oacc[nt][2] *= c1; oacc[nt][3] *= c1;
        }

        #pragma unroll
        for (int j = 0; j < 4; j++) {
            uint32_t phi[4], plo[4];
            phi[0] = pack_split2(sacc[2*j][0],   sacc[2*j][1],   plo[0]);
            phi[1] = pack_split2(sacc[2*j][2],   sacc[2*j][3],   plo[1]);
            phi[2] = pack_split2(sacc[2*j+1][0], sacc[2*j+1][1], plo[2]);
            phi[3] = pack_split2(sacc[2*j+1][2], sacc[2*j+1][3], plo[3]);
            #pragma unroll
            for (int half = 0; half < 2; half++) {
                uint32_t vh[4][4], vl[4][4];
                #pragma unroll
                for (int q4 = 0; q4 < 4; q4++) {
                    int np = half * 4 + q4;
                    uint32_t vaddr = ((j * 16 + (l & 15)) * SQel + np * 16 + ((l & 16) >> 1)) * 2;
                    ldsm4t(vh[q4], kb + 34816 + vaddr);
                    ldsm4t(vl[q4], kb + 52224 + vaddr);
                }
                #pragma unroll
                for (int q4 = 0; q4 < 4; q4++) {
                    int np = half * 4 + q4;
                    mma2(oacc[2*np],   phi, vh[q4][0], vh[q4][1]);
                    mma2(oacc[2*np+1], phi, vh[q4][2], vh[q4][3]);
                }
                #pragma unroll
                for (int q4 = 0; q4 < 4; q4++) {
                    int np = half * 4 + q4;
                    mma2(oacc[2*np],   phi, vl[q4][0], vl[q4][1]);
                    mma2(oacc[2*np+1], phi, vl[q4][2], vl[q4][3]);
                }
                #pragma unroll
                for (int q4 = 0; q4 < 4; q4++) {
                    int np = half * 4 + q4;
                    mma2(oacc[2*np],   plo, vh[q4][0], vh[q4][1]);
                    mma2(oacc[2*np+1], plo, vh[q4][2], vh[q4][3]);
                }
            }
        }
        __syncthreads();
    }

    float inv0 = 1.0f / lsum0, inv1 = 1.0f / lsum1;
    size_t base0 = ((size_t)(b * SEQ + qg0) * HQ + h) * HD;
    size_t base1 = base0 + (size_t)8 * HQ * HD;
    #pragma unroll
    for (int nt = 0; nt < 16; nt++) {
        int col = nt * 8 + (l & 3) * 2;
        uint32_t lo;
        uint32_t hi = pack_split2(oacc[nt][0] * inv0, oacc[nt][1] * inv0, lo);
        *(uint32_t*)&Ahi[base0 + col] = hi;
        *(uint32_t*)&Alo[base0 + col] = lo;
        hi = pack_split2(oacc[nt][2] * inv1, oacc[nt][3] * inv1, lo);
        *(uint32_t*)&Ahi[base1 + col] = hi;
        *(uint32_t*)&Alo[base1 + col] = lo;
    }
}

// ---------------------------------------------------------------------------
extern "C" void kernel_launch(void* const* d_in, const int* in_sizes, int n_in,
                              void* d_out, int out_size)
{
    const float* x  = (const float*)d_in[0];
    const float* wq = (const float*)d_in[1];
    const float* wk = (const float*)d_in[2];
    const float* wv = (const float*)d_in[3];
    const float* wo = (const float*)d_in[4];
    float* out = (float*)d_out;

    __nv_bfloat16 *xhi, *xlo, *qhi, *qlo, *khi, *klo, *vhi, *vlo, *ahi, *alo;
    __nv_bfloat16 *wqThi, *wqTlo, *wkThi, *wkTlo, *wvThi, *wvTlo, *woThi, *woTlo;
    cudaGetSymbolAddress((void**)&xhi, g_xhi);
    cudaGetSymbolAddress((void**)&xlo, g_xlo);
    cudaGetSymbolAddress((void**)&qhi, g_qhi);
    cudaGetSymbolAddress((void**)&qlo, g_qlo);
    cudaGetSymbolAddress((void**)&khi, g_khi);
    cudaGetSymbolAddress((void**)&klo, g_klo);
    cudaGetSymbolAddress((void**)&vhi, g_vhi);
    cudaGetSymbolAddress((void**)&vlo, g_vlo);
    cudaGetSymbolAddress((void**)&ahi, g_ahi);
    cudaGetSymbolAddress((void**)&alo, g_alo);
    cudaGetSymbolAddress((void**)&wqThi, g_wqThi);
    cudaGetSymbolAddress((void**)&wqTlo, g_wqTlo);
    cudaGetSymbolAddress((void**)&wkThi, g_wkThi);
    cudaGetSymbolAddress((void**)&wkTlo, g_wkTlo);
    cudaGetSymbolAddress((void**)&wvThi, g_wvThi);
    cudaGetSymbolAddress((void**)&wvTlo, g_wvTlo);
    cudaGetSymbolAddress((void**)&woThi, g_woThi);
    cudaGetSymbolAddress((void**)&woTlo, g_woTlo);

    cudaFuncSetAttribute(gemm_hmma, cudaFuncAttributeMaxDynamicSharedMemorySize,
                         GEMM_SMEM);
    cudaFuncSetAttribute(flash_hmma, cudaFuncAttributeMaxDynamicSharedMemorySize,
                         FLASH2_SMEM);

    const int n4 = ROWS * DIMV / 4;

    // Launch order arranged so a gemm_hmma sits at ncu capture slots (#4, #6).
    split_rm<<<n4 / 256, 256>>>((const float4*)x, xhi, xlo, n4);                      // 1
    transpose_split<<<dim3(DIMV / 32,  DIMV / 32), 256>>>(wq, wqThi, wqTlo, DIMV, DIMV);  // 2
    transpose_split<<<dim3(KVDIM / 32, DIMV / 32), 256>>>(wk, wkThi, wkTlo, DIMV, KVDIM); // 3
    gemm_hmma<<<dim3(DIMV / 128,  ROWS / 128), 256, GEMM_SMEM>>>(                     // 4
        xhi, xlo, wqThi, wqTlo, nullptr, qhi, qlo, ROWS, DIMV, DIMV);
    transpose_split<<<dim3(KVDIM / 32, DIMV / 32), 256>>>(wv, wvThi, wvTlo, DIMV, KVDIM); // 5
    gemm_hmma<<<dim3(KVDIM / 128, ROWS / 128), 256, GEMM_SMEM>>>(                     // 6
        xhi, xlo, wkThi, wkTlo, nullptr, khi, klo, ROWS, KVDIM, DIMV);
    transpose_split<<<dim3(DIMV / 32,  DIMV / 32), 256>>>(wo, woThi, woTlo, DIMV, DIMV);  // 7
    gemm_hmma<<<dim3(KVDIM / 128, ROWS / 128), 256, GEMM_SMEM>>>(                     // 8
        xhi, xlo, wvThi, wvTlo, nullptr, vhi, vlo, ROWS, KVDIM, DIMV);
    flash_hmma<<<dim3(SEQ / BQ2, HQ, BATCH), 256, FLASH2_SMEM>>>(                     // 9
        qhi, qlo, khi, klo, vhi, vlo, ahi, alo);
    gemm_hmma<<<dim3(DIMV / 128, ROWS / 128), 256, GEMM_SMEM>>>(                      // 10
        ahi, alo, woThi, woTlo, out, nullptr, nullptr, ROWS, DIMV, DIMV);
}

// round 12
// speedup vs baseline: 1.0225x; 1.0070x over previous
#include <cuda_runtime.h>
#include <cuda_bf16.h>
#include <cstdint>

// Problem constants
#define BATCH   2
#define SEQ     2048
#define DIMV    4096
#define HQ      32
#define HKV     8
#define HD      128
#define ROWS    (BATCH * SEQ)      // 4096
#define KVDIM   (HKV * HD)         // 1024
#define QKVN    (DIMV + 2 * KVDIM) // 6144: fused projection width
#define KOFF    DIMV               // col offset of K block in fused output
#define VOFF    (DIMV + KVDIM)     // col offset of V block

// ---------------------------------------------------------------------------
// Device scratch (allocation-free rule)
// ---------------------------------------------------------------------------
__device__ __nv_bfloat16 g_xhi[ROWS * DIMV],   g_xlo[ROWS * DIMV];
__device__ __nv_bfloat16 g_qkvhi[ROWS * QKVN], g_qkvlo[ROWS * QKVN];
__device__ __nv_bfloat16 g_ahi[ROWS * DIMV],   g_alo[ROWS * DIMV];
__device__ __nv_bfloat16 g_wqkvThi[QKVN * DIMV], g_wqkvTlo[QKVN * DIMV];
__device__ __nv_bfloat16 g_woThi[DIMV * DIMV],   g_woTlo[DIMV * DIMV];

// ---------------------------------------------------------------------------
// Arch-generic PTX helpers (NO 'a'-gated instructions: sm_103 virtual target)
// ---------------------------------------------------------------------------
__device__ __forceinline__ uint32_t smem_u32(const void* p) {
    uint32_t a;
    asm("{ .reg .u64 t; cvta.to.shared.u64 t, %1; cvt.u32.u64 %0, t; }"
        : "=r"(a) : "l"(p));
    return a;
}

#define CP_ASYNC16(saddr, gptr) \
    asm volatile("cp.async.cg.shared.global [%0], [%1], 16;" \
        :: "r"(saddr), "l"(gptr) : "memory")
#define CP_COMMIT()  asm volatile("cp.async.commit_group;" ::: "memory")
#define CP_WAIT1()   asm volatile("cp.async.wait_group 1;" ::: "memory")
#define CP_WAIT0()   asm volatile("cp.async.wait_group 0;" ::: "memory")

__device__ __forceinline__ void ldsm4(uint32_t* r, uint32_t addr) {
    asm volatile("ldmatrix.sync.aligned.m8n8.x4.shared.b16 {%0,%1,%2,%3}, [%4];"
        : "=r"(r[0]), "=r"(r[1]), "=r"(r[2]), "=r"(r[3]) : "r"(addr));
}
__device__ __forceinline__ void ldsm4t(uint32_t* r, uint32_t addr) {
    asm volatile("ldmatrix.sync.aligned.m8n8.x4.trans.shared.b16 {%0,%1,%2,%3}, [%4];"
        : "=r"(r[0]), "=r"(r[1]), "=r"(r[2]), "=r"(r[3]) : "r"(addr));
}

__device__ __forceinline__ void mma16816(float* d, const uint32_t* a, const uint32_t* b) {
    asm volatile("mma.sync.aligned.m16n8k16.row.col.f32.bf16.bf16.f32 "
        "{%0,%1,%2,%3}, {%4,%5,%6,%7}, {%8,%9}, {%0,%1,%2,%3};"
        : "+f"(d[0]), "+f"(d[1]), "+f"(d[2]), "+f"(d[3])
        : "r"(a[0]), "r"(a[1]), "r"(a[2]), "r"(a[3]), "r"(b[0]), "r"(b[1]));
}
__device__ __forceinline__ void mma2(float* d, const uint32_t* a, uint32_t b0, uint32_t b1) {
    asm volatile("mma.sync.aligned.m16n8k16.row.col.f32.bf16.bf16.f32 "
        "{%0,%1,%2,%3}, {%4,%5,%6,%7}, {%8,%9}, {%0,%1,%2,%3};"
        : "+f"(d[0]), "+f"(d[1]), "+f"(d[2]), "+f"(d[3])
        : "r"(a[0]), "r"(a[1]), "r"(a[2]), "r"(a[3]), "r"(b0), "r"(b1));
}

__device__ __forceinline__ uint32_t pack_split2(float a, float b, uint32_t& lo_out) {
    __nv_bfloat16 ha = __float2bfloat16(a), hb = __float2bfloat16(b);
    __nv_bfloat16 la = __float2bfloat16(a - __bfloat162float(ha));
    __nv_bfloat16 lb = __float2bfloat16(b - __bfloat162float(hb));
    __nv_bfloat162 H(ha, hb), L(la, lb);
    lo_out = *(uint32_t*)&L;
    return *(uint32_t*)&H;
}

// ---------------------------------------------------------------------------
// Split fp32 -> bf16 hi/lo (row-major, elementwise)
// ---------------------------------------------------------------------------
__global__ __launch_bounds__(256) void split_rm(
    const float4* __restrict__ in, __nv_bfloat16* __restrict__ hi,
    __nv_bfloat16* __restrict__ lo, int n4)
{
    int i = blockIdx.x * 256 + threadIdx.x;
    if (i >= n4) return;
    float4 v = in[i];
    uint32_t l0, l1;
    uint32_t h0 = pack_split2(v.x, v.y, l0);
    uint32_t h1 = pack_split2(v.z, v.w, l1);
    uint32_t* H = (uint32_t*)hi;
    uint32_t* L = (uint32_t*)lo;
    H[2*i] = h0; H[2*i+1] = h1;
    L[2*i] = l0; L[2*i+1] = l1;
}

// ---------------------------------------------------------------------------
// Transpose + split: W[K,N] fp32 -> WT_hi[N,K], WT_lo[N,K] bf16
// (callers may offset Thi/Tlo to place blocks in a fused weight buffer)
// ---------------------------------------------------------------------------
__global__ __launch_bounds__(256) void transpose_split(
    const float* __restrict__ W, __nv_bfloat16* __restrict__ Thi,
    __nv_bfloat16* __restrict__ Tlo, int K, int N)
{
    __shared__ float t[32][33];
    int tx = threadIdx.x & 31, ty = threadIdx.x >> 5;   // 32x8
    int n0 = blockIdx.x * 32, k0 = blockIdx.y * 32;
    #pragma unroll
    for (int i = 0; i < 32; i += 8)
        t[ty + i][tx] = W[(size_t)(k0 + ty + i) * N + n0 + tx];
    __syncthreads();
    #pragma unroll
    for (int i = 0; i < 32; i += 8) {
        float v = t[tx][ty + i];
        __nv_bfloat16 h = __float2bfloat16(v);
        __nv_bfloat16 l = __float2bfloat16(v - __bfloat162float(h));
        size_t o = (size_t)(n0 + ty + i) * K + k0 + tx;
        Thi[o] = h; Tlo[o] = l;
    }
}

// ---------------------------------------------------------------------------
// HMMA GEMM: C = A @ Bt^T, A/Bt bf16 hi/lo; 3 passes. Output fp32 (Cf) or
// fused-split bf16 hi/lo (Chi/Clo) when Cf == nullptr.
// CTA tile 128x128, 8 warps (32x64). BK=32, pad 40 (80B rows, conflict-free
// ldsm bank walk), 2 stages -> 81920B/CTA -> 2 CTAs/SM.
// ---------------------------------------------------------------------------
#define BK2 32
#define BKp2 40
#define TILE2_B (128 * BKp2 * 2)            // 10240
#define STAGE2_B (4 * TILE2_B)              // 40960
#define GEMM_SMEM (2 * STAGE2_B)            // 81920

__global__ __launch_bounds__(256, 2)
void gemm_hmma(const __nv_bfloat16* __restrict__ Ahi,
               const __nv_bfloat16* __restrict__ Alo,
               const __nv_bfloat16* __restrict__ Bhi,
               const __nv_bfloat16* __restrict__ Blo,
               float* __restrict__ Cf,
               __nv_bfloat16* __restrict__ Chi, __nv_bfloat16* __restrict__ Clo,
               int M, int N, int K)
{
    extern __shared__ char smem[];
    const uint32_t sb = smem_u32(smem);
    const int tid = threadIdx.x;
    const int m0 = blockIdx.y * 128, n0 = blockIdx.x * 128;
    const int l = tid & 31, w = tid >> 5;
    const int wm = (w & 3) * 32, wn = (w >> 2) * 64;
    const int NCH = K / BK2;

    float acc[2][8][4];
    #pragma unroll
    for (int mt = 0; mt < 2; mt++)
        #pragma unroll
        for (int nt = 0; nt < 8; nt++)
            #pragma unroll
            for (int e = 0; e < 4; e++) acc[mt][nt][e] = 0.0f;

    const __nv_bfloat16* srcs[4] = {Ahi, Alo, Bhi, Blo};

    #pragma unroll
    for (int it = 0; it < 8; it++) {
        int i = tid + it * 256;
        int a = i >> 9, j = i & 511;
        int r = j >> 2, s = j & 3;
        const int rb = (a < 2) ? m0 : n0;
        CP_ASYNC16(sb + a * TILE2_B + (r * BKp2 + s * 8) * 2,
                   srcs[a] + (size_t)(rb + r) * K + (s << 3));
    }
    CP_COMMIT();

    for (int c = 0; c < NCH; c++) {
        if (c + 1 < NCH) {
            const uint32_t st = ((c + 1) & 1) * STAGE2_B;
            #pragma unroll
            for (int it = 0; it < 8; it++) {
                int i = tid + it * 256;
                int a = i >> 9, j = i & 511;
                int r = j >> 2, s = j & 3;
                const int rb = (a < 2) ? m0 : n0;
                CP_ASYNC16(sb + st + a * TILE2_B + (r * BKp2 + s * 8) * 2,
                           srcs[a] + (size_t)(rb + r) * K + (c + 1) * BK2 + (s << 3));
            }
            CP_COMMIT();
            CP_WAIT1();
        } else {
            CP_WAIT0();
        }
        __syncthreads();

        const uint32_t sbase = sb + (c & 1) * STAGE2_B;
        #pragma unroll
        for (int pass = 0; pass < 3; pass++) {
            const uint32_t aoff = sbase + (pass == 2 ? TILE2_B : 0);
            const uint32_t boff = sbase + (pass == 1 ? 3 * TILE2_B : 2 * TILE2_B);
            #pragma unroll
            for (int kb = 0; kb < BK2; kb += 16) {
                uint32_t af[2][4], bf[8][2];
                #pragma unroll
                for (int mt = 0; mt < 2; mt++) {
                    int row = wm + mt * 16 + (l & 15);
                    int col = kb + ((l & 16) >> 1);
                    ldsm4(af[mt], aoff + (row * BKp2 + col) * 2);
                }
                #pragma unroll
                for (int nt2 = 0; nt2 < 4; nt2++) {
                    int row = wn + nt2 * 16 + (l & 7) + ((l & 16) >> 1);
                    int col = kb + (l & 8);
                    uint32_t r4[4];
                    ldsm4(r4, boff + (row * BKp2 + col) * 2);
                    bf[nt2 * 2][0] = r4[0];  bf[nt2 * 2][1] = r4[1];
                    bf[nt2 * 2 + 1][0] = r4[2];  bf[nt2 * 2 + 1][1] = r4[3];
                }
                #pragma unroll
                for (int mt = 0; mt < 2; mt++)
                    #pragma unroll
                    for (int nt = 0; nt < 8; nt++)
                        mma16816(acc[mt][nt], af[mt], bf[nt]);
            }
        }
        __syncthreads();
    }

    #pragma unroll
    for (int mt = 0; mt < 2; mt++) {
        int row = m0 + wm + mt * 16 + (l >> 2);
        #pragma unroll
        for (int nt = 0; nt < 8; nt++) {
            int col = n0 + wn + nt * 8 + (l & 3) * 2;
            if (Cf) {
                *(float2*)&Cf[(size_t)row * N + col] =
                    make_float2(acc[mt][nt][0], acc[mt][nt][1]);
                *(float2*)&Cf[(size_t)(row + 8) * N + col] =
                    make_float2(acc[mt][nt][2], acc[mt][nt][3]);
            } else {
                uint32_t lo;
                uint32_t hi = pack_split2(acc[mt][nt][0], acc[mt][nt][1], lo);
                *(uint32_t*)&Chi[(size_t)row * N + col] = hi;
                *(uint32_t*)&Clo[(size_t)row * N + col] = lo;
                hi = pack_split2(acc[mt][nt][2], acc[mt][nt][3], lo);
                *(uint32_t*)&Chi[(size_t)(row + 8) * N + col] = hi;
                *(uint32_t*)&Clo[(size_t)(row + 8) * N + col] = lo;
            }
        }
    }
}

// ---------------------------------------------------------------------------
// HMMA flash attention — reads Q/K/V from the FUSED qkv buffer (row stride
// QKVN; Q at col h*HD, K at KOFF + kvh*HD, V at VOFF + kvh*HD).
// ---------------------------------------------------------------------------
#define BQ2 128
#define BKV2 64
#define SQel 136
#define F_QHI 0
#define F_QLO 34816
#define F_STAGE0 69632
#define F_STAGE_SZ 69632
#define FLASH2_SMEM (F_STAGE0 + 2 * F_STAGE_SZ)   // 208896 B

__global__ __launch_bounds__(256, 1)
void flash_hmma(const __nv_bfloat16* __restrict__ QKVhi,
                const __nv_bfloat16* __restrict__ QKVlo,
                __nv_bfloat16* __restrict__ Ahi, __nv_bfloat16* __restrict__ Alo)
{
    extern __shared__ char smem[];
    const uint32_t sb = smem_u32(smem);
    const int qb = blockIdx.x, h = blockIdx.y, b = blockIdx.z;
    const int kvh = h >> 2;
    const int tid = threadIdx.x;
    const int l = tid & 31, w = tid >> 5;
    const int wq = w * 16;
    const float scale = 0.08838834764831845f;

    // Q load (once): 2 tiles (hi, lo) x 128 rows x 16 segs of 16B
    #pragma unroll
    for (int it = 0; it < 16; it++) {
        int idx = tid + it * 256;
        int t = idx >> 11, r = (idx >> 4) & 127, s = idx & 15;
        const __nv_bfloat16* src = t ? QKVlo : QKVhi;
        size_t grow = (size_t)(b * SEQ + qb * BQ2 + r) * QKVN + h * HD;
        CP_ASYNC16(sb + (t ? F_QLO : F_QHI) + (r * SQel + s * 8) * 2, src + grow + s * 8);
    }
    // K/V stage 0: t = 0:Khi 1:Klo 2:Vhi 3:Vlo
    #pragma unroll
    for (int it = 0; it < 16; it++) {
        int idx = tid + it * 256;
        int t = idx >> 10, r = (idx >> 4) & 63, s = idx & 15;
        const __nv_bfloat16* src = (t & 1) ? QKVlo : QKVhi;
        int coff = (t < 2 ? KOFF : VOFF) + kvh * HD;
        size_t grow = (size_t)(b * SEQ + r) * QKVN + coff;
        CP_ASYNC16(sb + F_STAGE0 + t * 17408 + (r * SQel + s * 8) * 2, src + grow + s * 8);
    }
    CP_COMMIT();

    float oacc[16][4];
    #pragma unroll
    for (int nt = 0; nt < 16; nt++)
        #pragma unroll
        for (int e = 0; e < 4; e++) oacc[nt][e] = 0.0f;
    float m0 = -1e30f, m1 = -1e30f, lsum0 = 0.0f, lsum1 = 0.0f;
    const int qg0 = qb * BQ2 + wq + (l >> 2);

    const int niter = 2 * (qb + 1);
    for (int kt = 0; kt < niter; kt++) {
        if (kt + 1 < niter) {
            uint32_t st = sb + F_STAGE0 + ((kt + 1) & 1) * F_STAGE_SZ;
            #pragma unroll
            for (int it = 0; it < 16; it++) {
                int idx = tid + it * 256;
                int t = idx >> 10, r = (idx >> 4) & 63, s = idx & 15;
                const __nv_bfloat16* src = (t & 1) ? QKVlo : QKVhi;
                int coff = (t < 2 ? KOFF : VOFF) + kvh * HD;
                size_t grow = (size_t)(b * SEQ + (kt + 1) * BKV2 + r) * QKVN + coff;
                CP_ASYNC16(st + t * 17408 + (r * SQel + s * 8) * 2, src + grow + s * 8);
            }
            CP_COMMIT();
            CP_WAIT1();
        } else {
            CP_WAIT0();
        }
        __syncthreads();
        const uint32_t kb = sb + F_STAGE0 + (kt & 1) * F_STAGE_SZ;

        float sacc[8][4];
        #pragma unroll
        for (int nt = 0; nt < 8; nt++)
            #pragma unroll
            for (int e = 0; e < 4; e++) sacc[nt][e] = 0.0f;

        #pragma unroll
        for (int ks = 0; ks < 8; ks++) {
            uint32_t ahi[4], alo[4];
            uint32_t aaddr = ((wq + (l & 15)) * SQel + ks * 16 + ((l & 16) >> 1)) * 2;
            ldsm4(ahi, sb + F_QHI + aaddr);
            ldsm4(alo, sb + F_QLO + aaddr);
            uint32_t bhi[8][2], blo[8][2];
            #pragma unroll
            for (int nt2 = 0; nt2 < 4; nt2++) {
                int row = nt2 * 16 + (l & 7) + ((l & 16) >> 1);
                int col = ks * 16 + (l & 8);
                uint32_t r4[4];
                ldsm4(r4, kb + (row * SQel + col) * 2);
                bhi[nt2*2][0] = r4[0]; bhi[nt2*2][1] = r4[1];
                bhi[nt2*2+1][0] = r4[2]; bhi[nt2*2+1][1] = r4[3];
                ldsm4(r4, kb + 17408 + (row * SQel + col) * 2);
                blo[nt2*2][0] = r4[0]; blo[nt2*2][1] = r4[1];
                blo[nt2*2+1][0] = r4[2]; blo[nt2*2+1][1] = r4[3];
            }
            #pragma unroll
            for (int nt = 0; nt < 8; nt++) mma16816(sacc[nt], ahi, bhi[nt]);
            #pragma unroll
            for (int nt = 0; nt < 8; nt++) mma16816(sacc[nt], ahi, blo[nt]);
            #pragma unroll
            for (int nt = 0; nt < 8; nt++) mma16816(sacc[nt], alo, bhi[nt]);
        }

        const bool domask = (kt >= 2 * qb);
        #pragma unroll
        for (int nt = 0; nt < 8; nt++)
            #pragma unroll
            for (int e = 0; e < 4; e++) {
                float s = sacc[nt][e] * scale;
                if (domask) {
                    int kg = kt * BKV2 + nt * 8 + (l & 3) * 2 + (e & 1);
                    int qg = qg0 + ((e >= 2) ? 8 : 0);
                    if (kg > qg) s = -1e30f;
                }
                sacc[nt][e] = s;
            }
        float mx0 = -1e30f, mx1 = -1e30f;
        #pragma unroll
        for (int nt = 0; nt < 8; nt++) {
            mx0 = fmaxf(mx0, fmaxf(sacc[nt][0], sacc[nt][1]));
            mx1 = fmaxf(mx1, fmaxf(sacc[nt][2], sacc[nt][3]));
        }
        mx0 = fmaxf(mx0, __shfl_xor_sync(0xffffffffu, mx0, 1));
        mx0 = fmaxf(mx0, __shfl_xor_sync(0xffffffffu, mx0, 2));
        mx1 = fmaxf(mx1, __shfl_xor_sync(0xffffffffu, mx1, 1));
        mx1 = fmaxf(mx1, __shfl_xor_sync(0xffffffffu, mx1, 2));
        float mn0 = fmaxf(m0, mx0), mn1 = fmaxf(m1, mx1);
        float c0 = __expf(m0 - mn0), c1 = __expf(m1 - mn1);
        m0 = mn0; m1 = mn1;
        float ps0 = 0.0f, ps1 = 0.0f;
        #pragma unroll
        for (int nt = 0; nt < 8; nt++) {
            float p0 = __expf(sacc[nt][0] - mn0), p1 = __expf(sacc[nt][1] - mn0);
            float p2 = __expf(sacc[nt][2] - mn1), p3 = __expf(sacc[nt][3] - mn1);
            ps0 += p0 + p1; ps1 += p2 + p3;
            sacc[nt][0] = p0; sacc[nt][1] = p1; sacc[nt][2] = p2; sacc[nt][3] = p3;
        }
        ps0 += __shfl_xor_sync(0xffffffffu, ps0, 1);
        ps0 += __shfl_xor_sync(0xffffffffu, ps0, 2);
        ps1 += __shfl_xor_sync(0xffffffffu, ps1, 1);
        ps1 += __shfl_xor_sync(0xffffffffu, ps1, 2);
        lsum0 = lsum0 * c0 + ps0;
        lsum1 = lsum1 * c1 + ps1;
        #pragma unroll
        for (int nt = 0; nt < 16; nt++) {
            oacc[nt][0] *= c0; oacc[nt][1] *= c0;
            oacc[nt][2] *= c1; oacc[nt][3] *= c1;
        }

        #pragma unroll
        for (int j = 0; j < 4; j++) {
            uint32_t phi[4], plo[4];
            phi[0] = pack_split2(sacc[2*j][0],   sacc[2*j][1],   plo[0]);
            phi[1] = pack_split2(sacc[2*j][2],   sacc[2*j][3],   plo[1]);
            phi[2] = pack_split2(sacc[2*j+1][0], sacc[2*j+1][1], plo[2]);
            phi[3] = pack_split2(sacc[2*j+1][2], sacc[2*j+1][3], plo[3]);
            #pragma unroll
            for (int half = 0; half < 2; half++) {
                uint32_t vh[4][4], vl[4][4];
                #pragma unroll
                for (int q4 = 0; q4 < 4; q4++) {
                    int np = half * 4 + q4;
                    uint32_t vaddr = ((j * 16 + (l & 15)) * SQel + np * 16 + ((l & 16) >> 1)) * 2;
                    ldsm4t(vh[q4], kb + 34816 + vaddr);
                    ldsm4t(vl[q4], kb + 52224 + vaddr);
                }
                #pragma unroll
                for (int q4 = 0; q4 < 4; q4++) {
                    int np = half * 4 + q4;
                    mma2(oacc[2*np],   phi, vh[q4][0], vh[q4][1]);
                    mma2(oacc[2*np+1], phi, vh[q4][2], vh[q4][3]);
                }
                #pragma unroll
                for (int q4 = 0; q4 < 4; q4++) {
                    int np = half * 4 + q4;
                    mma2(oacc[2*np],   phi, vl[q4][0], vl[q4][1]);
                    mma2(oacc[2*np+1], phi, vl[q4][2], vl[q4][3]);
                }
                #pragma unroll
                for (int q4 = 0; q4 < 4; q4++) {
                    int np = half * 4 + q4;
                    mma2(oacc[2*np],   plo, vh[q4][0], vh[q4][1]);
                    mma2(oacc[2*np+1], plo, vh[q4][2], vh[q4][3]);
                }
            }
        }
        __syncthreads();
    }

    // Output att in [B,S,HQ,HD] (= ROWS x DIMV) hi/lo splits
    float inv0 = 1.0f / lsum0, inv1 = 1.0f / lsum1;
    size_t base0 = ((size_t)(b * SEQ + qg0) * HQ + h) * HD;
    size_t base1 = base0 + (size_t)8 * HQ * HD;
    #pragma unroll
    for (int nt = 0; nt < 16; nt++) {
        int col = nt * 8 + (l & 3) * 2;
        uint32_t lo;
        uint32_t hi = pack_split2(oacc[nt][0] * inv0, oacc[nt][1] * inv0, lo);
        *(uint32_t*)&Ahi[base0 + col] = hi;
        *(uint32_t*)&Alo[base0 + col] = lo;
        hi = pack_split2(oacc[nt][2] * inv1, oacc[nt][3] * inv1, lo);
        *(uint32_t*)&Ahi[base1 + col] = hi;
        *(uint32_t*)&Alo[base1 + col] = lo;
    }
}

// ---------------------------------------------------------------------------
extern "C" void kernel_launch(void* const* d_in, const int* in_sizes, int n_in,
                              void* d_out, int out_size)
{
    const float* x  = (const float*)d_in[0];
    const float* wq = (const float*)d_in[1];
    const float* wk = (const float*)d_in[2];
    const float* wv = (const float*)d_in[3];
    const float* wo = (const float*)d_in[4];
    float* out = (float*)d_out;

    __nv_bfloat16 *xhi, *xlo, *qkvhi, *qkvlo, *ahi, *alo;
    __nv_bfloat16 *wqkvThi, *wqkvTlo, *woThi, *woTlo;
    cudaGetSymbolAddress((void**)&xhi, g_xhi);
    cudaGetSymbolAddress((void**)&xlo, g_xlo);
    cudaGetSymbolAddress((void**)&qkvhi, g_qkvhi);
    cudaGetSymbolAddress((void**)&qkvlo, g_qkvlo);
    cudaGetSymbolAddress((void**)&ahi, g_ahi);
    cudaGetSymbolAddress((void**)&alo, g_alo);
    cudaGetSymbolAddress((void**)&wqkvThi, g_wqkvThi);
    cudaGetSymbolAddress((void**)&wqkvTlo, g_wqkvTlo);
    cudaGetSymbolAddress((void**)&woThi, g_woThi);
    cudaGetSymbolAddress((void**)&woTlo, g_woTlo);

    cudaFuncSetAttribute(gemm_hmma, cudaFuncAttributeMaxDynamicSharedMemorySize,
                         GEMM_SMEM);
    cudaFuncSetAttribute(flash_hmma, cudaFuncAttributeMaxDynamicSharedMemorySize,
                         FLASH2_SMEM);

    const int n4 = ROWS * DIMV / 4;

    // Fused weight buffer: rows [0,4096)=wqT, [4096,5120)=wkT, [5120,6144)=wvT
    split_rm<<<n4 / 256, 256>>>((const float4*)x, xhi, xlo, n4);                          // 1
    transpose_split<<<dim3(DIMV / 32,  DIMV / 32), 256>>>(wq, wqkvThi, wqkvTlo,
                                                          DIMV, DIMV);                    // 2
    transpose_split<<<dim3(KVDIM / 32, DIMV / 32), 256>>>(wk,
        wqkvThi + (size_t)KOFF * DIMV, wqkvTlo + (size_t)KOFF * DIMV, DIMV, KVDIM);       // 3
    transpose_split<<<dim3(KVDIM / 32, DIMV / 32), 256>>>(wv,
        wqkvThi + (size_t)VOFF * DIMV, wqkvTlo + (size_t)VOFF * DIMV, DIMV, KVDIM);       // 4
    transpose_split<<<dim3(DIMV / 32,  DIMV / 32), 256>>>(wo, woThi, woTlo, DIMV, DIMV);  // 5

    // ONE fused QKV projection: [4096 x 6144] = x @ [wq|wk|wv]
    gemm_hmma<<<dim3(QKVN / 128, ROWS / 128), 256, GEMM_SMEM>>>(                          // 6
        xhi, xlo, wqkvThi, wqkvTlo, nullptr, qkvhi, qkvlo, ROWS, QKVN, DIMV);

    flash_hmma<<<dim3(SEQ / BQ2, HQ, BATCH), 256, FLASH2_SMEM>>>(                         // 7
        qkvhi, qkvlo, ahi, alo);

    gemm_hmma<<<dim3(DIMV / 128, ROWS / 128), 256, GEMM_SMEM>>>(                          // 8
        ahi, alo, woThi, woTlo, out, nullptr, nullptr, ROWS, DIMV, DIMV);
}